// round 3
// baseline (speedup 1.0000x reference)
#include <cuda_runtime.h>

#define HH 512
#define WW 512
#define NIMG 128      // B*C = 8*16
#define EPS_F 0.01f
#define OUTW 26       // valid output columns per 32-lane warp (3-lane halo each side)
#define STRIPS 20     // 20*26 = 520 >= 512
#define CHUNK 128
#define CHUNKS 4      // 512/128
#define WPB 8
#define THREADS 256

__global__ __launch_bounds__(THREADS, 4)
void guided_filter_kernel(const float* __restrict__ gI,
                          const float* __restrict__ gP,
                          float* __restrict__ gO)
{
    const int lane = threadIdx.x & 31;
    const int warp = threadIdx.x >> 5;
    int unit = blockIdx.x * WPB + warp;          // exact grid: units = STRIPS*CHUNKS*NIMG
    const int strip = unit % STRIPS;
    unit /= STRIPS;
    const int chunk = unit % CHUNKS;
    const int img   = unit / CHUNKS;

    const int c = strip * OUTW - 3 + lane;       // this lane's image column
    const bool cvalid = (c >= 0) && (c < WW);
    // 1/nw for count_include_pad=False (nw = valid cols in 3-window)
    const float inv_nw = (c >= 1 && c <= WW - 2) ? (1.0f / 3.0f)
                       : ((c == 0 || c == WW - 1) ? 0.5f : 1.0f);

    const long base = (long)img * (HH * WW) + c;
    const float* pI = gI + base;
    const float* pP = gP + base;
    float*       pO = gO + base;

    const int r0 = chunk * CHUNK;

    // register rings (period 3 — rotated away by unroll 6)
    float i0 = 0.f, i1 = 0.f, i2 = 0.f;
    float hI0 = 0.f, hI1 = 0.f, hI2 = 0.f;
    float hP0 = 0.f, hP1 = 0.f, hP2 = 0.f;
    float hII0 = 0.f, hII1 = 0.f, hII2 = 0.f;
    float hIp0 = 0.f, hIp1 = 0.f, hIp2 = 0.f;
    float ha0 = 0.f, ha1 = 0.f, ha2 = 0.f;
    float hb0 = 0.f, hb1 = 0.f, hb2 = 0.f;

    const int s0 = r0 - 2;
    float i_nxt = (cvalid && s0 >= 0) ? pI[s0 * WW] : 0.0f;
    float p_nxt = (cvalid && s0 >= 0) ? pP[s0 * WW] : 0.0f;

    const unsigned FULL = 0xffffffffu;

    #pragma unroll 6
    for (int it = 0; it < CHUNK + 4; ++it) {     // 132 iterations, divisible by 6
        const int s = s0 + it;                   // row just loaded
        const float iv = i_nxt;
        const float pv = p_nxt;

        // prefetch next row (zero-fill outside image)
        {
            const int rn = s + 1;
            const bool lv = cvalid && (rn >= 0) && (rn < HH);
            i_nxt = lv ? pI[rn * WW] : 0.0f;
            p_nxt = lv ? pP[rn * WW] : 0.0f;
        }

        i0 = i1; i1 = i2; i2 = iv;               // keep I for the lagged output row

        // horizontal sums for row s: shuffle only raw i,p (4 shuffles)
        const float il = __shfl_up_sync(FULL, iv, 1);
        const float ir = __shfl_down_sync(FULL, iv, 1);
        const float pl = __shfl_up_sync(FULL, pv, 1);
        const float pr = __shfl_down_sync(FULL, pv, 1);

        hI0 = hI1;  hI1 = hI2;  hI2 = il + iv + ir;
        hP0 = hP1;  hP1 = hP2;  hP2 = pl + pv + pr;
        hII0 = hII1; hII1 = hII2; hII2 = il * il + iv * iv + ir * ir;
        hIp0 = hIp1; hIp1 = hIp2; hIp2 = il * pl + iv * pv + ir * pr;

        // a,b at row ra = s-1 (vertical sum of h-rings)
        const int ra = s - 1;
        const float inv_nh_a = ((unsigned)(ra - 1) <= (unsigned)(HH - 3)) ? (1.0f / 3.0f)
                             : ((ra == 0 || ra == HH - 1) ? 0.5f : 1.0f);
        const float invca = inv_nh_a * inv_nw;
        const float mI  = (hI0 + hI1 + hI2) * invca;
        const float mP  = (hP0 + hP1 + hP2) * invca;
        const float varI = (hII0 + hII1 + hII2) * invca - mI * mI;
        const float cov  = (hIp0 + hIp1 + hIp2) * invca - mI * mP;
        float a = __fdividef(cov, varI + EPS_F);
        float b = mP - a * mI;

        // CRITICAL: a,b are ZERO outside the image for the second blur
        // (box_sum pads with 0; counts exclude pad). Phantom rows/cols must
        // not pollute mean_a/mean_b at image borders.
        const bool ab_valid = cvalid && (ra >= 0) && (ra < HH);
        a = ab_valid ? a : 0.0f;
        b = ab_valid ? b : 0.0f;

        const float al = __shfl_up_sync(FULL, a, 1);
        const float ar = __shfl_down_sync(FULL, a, 1);
        const float bl = __shfl_up_sync(FULL, b, 1);
        const float br = __shfl_down_sync(FULL, b, 1);

        ha0 = ha1; ha1 = ha2; ha2 = al + a + ar;
        hb0 = hb1; hb1 = hb2; hb2 = bl + b + br;

        // output at row ro = s-2
        const int ro = s - 2;
        const float inv_nh_o = ((unsigned)(ro - 1) <= (unsigned)(HH - 3)) ? (1.0f / 3.0f)
                             : ((ro == 0 || ro == HH - 1) ? 0.5f : 1.0f);
        const float invco = inv_nh_o * inv_nw;
        const float ma = (ha0 + ha1 + ha2) * invco;
        const float mb = (hb0 + hb1 + hb2) * invco;
        const float outv = ma * i0 + mb;

        if (lane >= 3 && lane <= 28 && c < WW && ro >= r0 && ro < r0 + CHUNK) {
            pO[ro * WW] = outv;
        }
    }
}

extern "C" void kernel_launch(void* const* d_in, const int* in_sizes, int n_in,
                              void* d_out, int out_size) {
    const float* I = (const float*)d_in[0];   // input
    const float* P = (const float*)d_in[1];   // guide
    float* O = (float*)d_out;
    const int units  = STRIPS * CHUNKS * NIMG;   // 10240 warps
    const int blocks = units / WPB;              // 1280
    guided_filter_kernel<<<blocks, THREADS>>>(I, P, O);
}

// round 7
// speedup vs baseline: 1.5984x; 1.5984x over previous
#include <cuda_runtime.h>

#define HH 512
#define WW 512
#define NIMG 128      // B*C
#define OUTW 120      // output cols per warp (lanes 1..30, 4 cols each)
#define STRIPS 5      // 5*120 = 600 >= 512
#define CHUNK 64
#define CHUNKS 8      // 8*64 = 512
#define WPB 8
#define THREADS 256

typedef unsigned long long u64;

__device__ __forceinline__ u64 PK(float l, float h){u64 r; asm("mov.b64 %0,{%1,%2};":"=l"(r):"f"(l),"f"(h)); return r;}
__device__ __forceinline__ float LOF(u64 v){float a,b; asm("mov.b64 {%0,%1},%2;":"=f"(a),"=f"(b):"l"(v)); return a;}
__device__ __forceinline__ float HIF(u64 v){float a,b; asm("mov.b64 {%0,%1},%2;":"=f"(a),"=f"(b):"l"(v)); return b;}
__device__ __forceinline__ u64 ADD2(u64 a,u64 b){u64 r; asm("add.rn.f32x2 %0,%1,%2;":"=l"(r):"l"(a),"l"(b)); return r;}
__device__ __forceinline__ u64 MUL2(u64 a,u64 b){u64 r; asm("mul.rn.f32x2 %0,%1,%2;":"=l"(r):"l"(a),"l"(b)); return r;}
__device__ __forceinline__ u64 FMA2(u64 a,u64 b,u64 c){u64 r; asm("fma.rn.f32x2 %0,%1,%2,%3;":"=l"(r):"l"(a),"l"(b),"l"(c)); return r;}

#define NEG1C 0xBF800000BF800000ull      /* (-1, -1) */
#define EPS2C 0x3C23D70A3C23D70Aull      /* (0.01f, 0.01f) */

__global__ __launch_bounds__(THREADS, 2)
void gf4_kernel(const float* __restrict__ gI,
                const float* __restrict__ gP,
                float* __restrict__ gO)
{
    const int lane = threadIdx.x & 31;
    const int warp = threadIdx.x >> 5;
    int unit = blockIdx.x * WPB + warp;      // grid exactly STRIPS*CHUNKS*NIMG/WPB blocks
    const int strip = unit % STRIPS; unit /= STRIPS;
    const int chunk = unit % CHUNKS;
    const int img   = unit / CHUNKS;

    const int base  = strip * OUTW - 4 + 4 * lane;     // first of this lane's 4 cols
    const bool colok = (base >= 0) && (base < WW);     // whole-float4 validity (base%4==0)

    // per-element 1/nw for count_include_pad=False
    float inw[4];
    #pragma unroll
    for (int j = 0; j < 4; ++j) {
        const int cc = base + j;
        inw[j] = (cc >= 1 && cc <= WW - 2) ? (1.0f/3.0f)
               : ((cc == 0 || cc == WW - 1) ? 0.5f : 1.0f);
    }
    const u64 inwA = PK(inw[0], inw[1]);
    const u64 inwB = PK(inw[2], inw[3]);

    const long ib = (long)img * (HH * WW) + base;
    const float* pI = gI + ib;
    const float* pP = gP + ib;
    float*       pO = gO + ib;

    const int r0 = chunk * CHUNK;
    const int s0 = r0 - 2;

    // rings (period 3, renamed away by unroll)
    u64 hIa0=0,hIa1=0,hIa2=0,  hIb0=0,hIb1=0,hIb2=0;
    u64 hPa0=0,hPa1=0,hPa2=0,  hPb0=0,hPb1=0,hPb2=0;
    u64 hIIa0=0,hIIa1=0,hIIa2=0, hIIb0=0,hIIb1=0,hIIb2=0;
    u64 hIpa0=0,hIpa1=0,hIpa2=0, hIpb0=0,hIpb1=0,hIpb2=0;
    u64 gAa0=0,gAa1=0,gAa2=0,  gAb0=0,gAb1=0,gAb2=0;   // blur-of-a
    u64 gBa0=0,gBa1=0,gBa2=0,  gBb0=0,gBb1=0,gBb2=0;   // blur-of-b

    // prefetch row s0
    u64 ni01=0, ni23=0, np01=0, np23=0;
    if (colok && s0 >= 0) {
        const ulonglong2 ti = *(const ulonglong2*)(pI + (long)s0 * WW);
        const ulonglong2 tp = *(const ulonglong2*)(pP + (long)s0 * WW);
        ni01 = ti.x; ni23 = ti.y; np01 = tp.x; np23 = tp.y;
    }

    const unsigned FULL = 0xffffffffu;

    #pragma unroll 3
    for (int it = 0; it < CHUNK + 4; ++it) {
        const int s = s0 + it;                 // row just loaded
        const u64 vi01 = ni01, vi23 = ni23, vp01 = np01, vp23 = np23;

        // prefetch row s+1 (zero-fill outside image)
        {
            const int rn = s + 1;
            if (colok && (unsigned)rn < (unsigned)HH) {
                const ulonglong2 ti = *(const ulonglong2*)(pI + (long)rn * WW);
                const ulonglong2 tp = *(const ulonglong2*)(pP + (long)rn * WW);
                ni01 = ti.x; ni23 = ti.y; np01 = tp.x; np23 = tp.y;
            } else { ni01 = 0; ni23 = 0; np01 = 0; np23 = 0; }
        }

        // scalar components + neighbor shuffles (raw fields only)
        const float x0 = LOF(vi01), x1 = HIF(vi01), x2 = LOF(vi23), x3 = HIF(vi23);
        const float y0 = LOF(vp01), y1 = HIF(vp01), y2 = LOF(vp23), y3 = HIF(vp23);
        const float iL = __shfl_up_sync(FULL, x3, 1);
        const float iR = __shfl_down_sync(FULL, x0, 1);
        const float pL = __shfl_up_sync(FULL, y3, 1);
        const float pR = __shfl_down_sync(FULL, y0, 1);

        // shifted pairs (cols -1..2 and 1..4)
        const u64 siL = PK(iL, x0), siM = PK(x1, x2), siR = PK(x3, iR);
        const u64 spL = PK(pL, y0), spM = PK(y1, y2), spR = PK(y3, pR);

        // horizontal 3-sums (packed), push rings
        hIa0=hIa1; hIa1=hIa2;   hIa2 = ADD2(ADD2(siL, vi01), siM);
        hIb0=hIb1; hIb1=hIb2;   hIb2 = ADD2(ADD2(siM, vi23), siR);
        hPa0=hPa1; hPa1=hPa2;   hPa2 = ADD2(ADD2(spL, vp01), spM);
        hPb0=hPb1; hPb1=hPb2;   hPb2 = ADD2(ADD2(spM, vp23), spR);
        hIIa0=hIIa1; hIIa1=hIIa2; hIIa2 = FMA2(siL,siL, FMA2(vi01,vi01, MUL2(siM,siM)));
        hIIb0=hIIb1; hIIb1=hIIb2; hIIb2 = FMA2(siM,siM, FMA2(vi23,vi23, MUL2(siR,siR)));
        hIpa0=hIpa1; hIpa1=hIpa2; hIpa2 = FMA2(siL,spL, FMA2(vi01,vp01, MUL2(siM,spM)));
        hIpb0=hIpb1; hIpb1=hIpb2; hIpb2 = FMA2(siM,spM, FMA2(vi23,vp23, MUL2(siR,spR)));

        // a,b at row ra = s-1
        const int ra = s - 1;
        const float ih_a = ((unsigned)(ra - 1) <= (unsigned)(HH - 3)) ? (1.0f/3.0f)
                         : ((ra == 0 || ra == HH - 1) ? 0.5f : 1.0f);
        const u64 ih2 = PK(ih_a, ih_a);
        const u64 ivA = MUL2(ih2, inwA), ivB = MUL2(ih2, inwB);

        const u64 sIA  = ADD2(ADD2(hIa0, hIa1), hIa2);
        const u64 sIB  = ADD2(ADD2(hIb0, hIb1), hIb2);
        const u64 sPA  = ADD2(ADD2(hPa0, hPa1), hPa2);
        const u64 sPB  = ADD2(ADD2(hPb0, hPb1), hPb2);
        const u64 sIIA = ADD2(ADD2(hIIa0, hIIa1), hIIa2);
        const u64 sIIB = ADD2(ADD2(hIIb0, hIIb1), hIIb2);
        const u64 sIpA = ADD2(ADD2(hIpa0, hIpa1), hIpa2);
        const u64 sIpB = ADD2(ADD2(hIpb0, hIpb1), hIpb2);

        const u64 mIA = MUL2(sIA, ivA), mIB = MUL2(sIB, ivB);
        const u64 mPA = MUL2(sPA, ivA), mPB = MUL2(sPB, ivB);
        const u64 denA = FMA2(MUL2(mIA, mIA), NEG1C, FMA2(sIIA, ivA, EPS2C));
        const u64 denB = FMA2(MUL2(mIB, mIB), NEG1C, FMA2(sIIB, ivB, EPS2C));
        const u64 covA = FMA2(MUL2(mIA, mPA), NEG1C, MUL2(sIpA, ivA));
        const u64 covB = FMA2(MUL2(mIB, mPB), NEG1C, MUL2(sIpB, ivB));

        const float a0 = __fdividef(LOF(covA), LOF(denA));
        const float a1 = __fdividef(HIF(covA), HIF(denA));
        const float a2 = __fdividef(LOF(covB), LOF(denB));
        const float a3 = __fdividef(HIF(covB), HIF(denB));
        u64 aA = PK(a0, a1), aB = PK(a2, a3);
        u64 bA = FMA2(MUL2(aA, mIA), NEG1C, mPA);
        u64 bB = FMA2(MUL2(aB, mIB), NEG1C, mPB);

        // a,b are ZERO outside the image for the second blur
        const bool abok = colok && ((unsigned)ra < (unsigned)HH);
        aA = abok ? aA : 0ull;  aB = abok ? aB : 0ull;
        bA = abok ? bA : 0ull;  bB = abok ? bB : 0ull;

        const float aLs = __shfl_up_sync(FULL, HIF(aB), 1);
        const float aRs = __shfl_down_sync(FULL, LOF(aA), 1);
        const float bLs = __shfl_up_sync(FULL, HIF(bB), 1);
        const float bRs = __shfl_down_sync(FULL, LOF(bA), 1);

        const u64 saL = PK(aLs, LOF(aA)), saM = PK(HIF(aA), LOF(aB)), saR = PK(HIF(aB), aRs);
        const u64 sbL = PK(bLs, LOF(bA)), sbM = PK(HIF(bA), LOF(bB)), sbR = PK(HIF(bB), bRs);

        gAa0=gAa1; gAa1=gAa2;  gAa2 = ADD2(ADD2(saL, aA), saM);
        gAb0=gAb1; gAb1=gAb2;  gAb2 = ADD2(ADD2(saM, aB), saR);
        gBa0=gBa1; gBa1=gBa2;  gBa2 = ADD2(ADD2(sbL, bA), sbM);
        gBb0=gBb1; gBb1=gBb2;  gBb2 = ADD2(ADD2(sbM, bB), sbR);

        // output at row ro = s-2
        const int ro = s - 2;
        if (lane >= 1 && lane <= 30 && colok && ro >= r0 && ro < r0 + CHUNK) {
            const float ih_o = ((unsigned)(ro - 1) <= (unsigned)(HH - 3)) ? (1.0f/3.0f)
                             : ((ro == 0 || ro == HH - 1) ? 0.5f : 1.0f);
            const u64 io2 = PK(ih_o, ih_o);
            const u64 ioA = MUL2(io2, inwA), ioB = MUL2(io2, inwB);

            const u64 maA = MUL2(ADD2(ADD2(gAa0, gAa1), gAa2), ioA);
            const u64 maB = MUL2(ADD2(ADD2(gAb0, gAb1), gAb2), ioB);
            const u64 mbA = MUL2(ADD2(ADD2(gBa0, gBa1), gBa2), ioA);
            const u64 mbB = MUL2(ADD2(ADD2(gBb0, gBb1), gBb2), ioB);

            // reload I at the output row (L1 hit; saves the 3-deep I ring)
            const ulonglong2 tio = *(const ulonglong2*)(pI + (long)ro * WW);
            ulonglong2 ov;
            ov.x = FMA2(maA, tio.x, mbA);
            ov.y = FMA2(maB, tio.y, mbB);
            *(ulonglong2*)(pO + (long)ro * WW) = ov;
        }
    }
}

extern "C" void kernel_launch(void* const* d_in, const int* in_sizes, int n_in,
                              void* d_out, int out_size) {
    const float* I = (const float*)d_in[0];   // input
    const float* P = (const float*)d_in[1];   // guide
    float* O = (float*)d_out;
    const int units  = STRIPS * CHUNKS * NIMG;   // 5120 warps
    const int blocks = units / WPB;              // 640
    gf4_kernel<<<blocks, THREADS>>>(I, P, O);
}